// round 7
// baseline (speedup 1.0000x reference)
#include <cuda_runtime.h>

// Problem constants
static constexpr int Tt = 4;
static constexpr int Bb = 16;
static constexpr int Cc = 512;
static constexpr int Nn = 1024;
static constexpr int Cr = 64;
static constexpr int TB = Tt * Bb;     // 64 rows
static constexpr int BC = Bb * Cc;     // 8192 channels
static constexpr int NTASK = BC / 2;   // 4096 two-channel tasks

// Scratch (allocation-free: __device__ globals)
__device__ float g_buf[TB * Cc];       // GAP output [64, 512] row-major [r][c]
__device__ float h1nT_buf[Cr * TB];    // bn1 output TRANSPOSED [j][r]
// Monotonic grid-barrier state for the tail kernel (TAIL_NB arrivals per
// launch -> counter is a multiple of TAIL_NB at every launch start; barrier
// id B = ceil(v/TAIL_NB) is launch-count independent).
__device__ unsigned g_arrive;
__device__ volatile unsigned g_release;

static constexpr int TAIL_NB = 64;

// Shared union layout for tail kernel:
//   phase B: ws[512], h1s[64], stats[2]                    (<= 578)
//   phase C: hT[64*65]=4160, w2s[512], wsum[32]            (= 4704)
static constexpr int SH_FLOATS = 64 * 65 + 512 + 32;   // 4704

// ---------------------------------------------------------------------------
// K1: LIF multistep (TAU=2, hard reset, v_th=1) + GAP over N.
// Persistent grid-stride over 4096 tasks; per task: 2 channels, 256 threads,
// 8 front-batched LDG.128 per thread (R2-proven inner shape).
// ---------------------------------------------------------------------------
__global__ void __launch_bounds__(256) lif_gap_kernel(const float* __restrict__ x,
                                                      int nb) {
    const int tid  = threadIdx.x;
    const int lane = tid & 31;
    const int warp = tid >> 5;
    const float4* __restrict__ xp = reinterpret_cast<const float4*>(x);

    __shared__ float sdata[8][8];   // [warp][val]

    for (int task = blockIdx.x; task < NTASK; task += nb) {
        const int bc0 = task * 2;
        const int bc1 = bc0 + 1;

        float4 xa[Tt], xb[Tt];
        #pragma unroll
        for (int t = 0; t < Tt; t++) {
            xa[t] = xp[(size_t)(t * BC + bc0) * 256 + tid];
            xb[t] = xp[(size_t)(t * BC + bc1) * 256 + tid];
        }

        float va0=0.f, va1=0.f, va2=0.f, va3=0.f;
        float vb0=0.f, vb1=0.f, vb2=0.f, vb3=0.f;
        float c8[8];

        #pragma unroll
        for (int t = 0; t < Tt; t++) {
            float ca = 0.f, cb = 0.f;
            va0 = (va0 + xa[t].x) * 0.5f; { float s = (va0 >= 1.f) ? 1.f : 0.f; ca += s; va0 *= (1.f - s); }
            va1 = (va1 + xa[t].y) * 0.5f; { float s = (va1 >= 1.f) ? 1.f : 0.f; ca += s; va1 *= (1.f - s); }
            va2 = (va2 + xa[t].z) * 0.5f; { float s = (va2 >= 1.f) ? 1.f : 0.f; ca += s; va2 *= (1.f - s); }
            va3 = (va3 + xa[t].w) * 0.5f; { float s = (va3 >= 1.f) ? 1.f : 0.f; ca += s; va3 *= (1.f - s); }
            vb0 = (vb0 + xb[t].x) * 0.5f; { float s = (vb0 >= 1.f) ? 1.f : 0.f; cb += s; vb0 *= (1.f - s); }
            vb1 = (vb1 + xb[t].y) * 0.5f; { float s = (vb1 >= 1.f) ? 1.f : 0.f; cb += s; vb1 *= (1.f - s); }
            vb2 = (vb2 + xb[t].z) * 0.5f; { float s = (vb2 >= 1.f) ? 1.f : 0.f; cb += s; vb2 *= (1.f - s); }
            vb3 = (vb3 + xb[t].w) * 0.5f; { float s = (vb3 >= 1.f) ? 1.f : 0.f; cb += s; vb3 *= (1.f - s); }
            c8[t]     = ca;
            c8[t + 4] = cb;
        }

        #pragma unroll
        for (int k = 0; k < 8; k++) {
            float val = c8[k];
            #pragma unroll
            for (int off = 16; off > 0; off >>= 1)
                val += __shfl_down_sync(0xffffffffu, val, off);
            if (lane == 0) sdata[warp][k] = val;
        }
        __syncthreads();

        if (tid < 8) {
            float s = 0.f;
            #pragma unroll
            for (int w = 0; w < 8; w++) s += sdata[w][tid];
            const int t  = tid & 3;
            const int bc = (tid < 4) ? bc0 : bc1;
            g_buf[t * BC + bc] = s * (1.0f / (float)Nn);
        }
        __syncthreads();   // protect sdata for next task
    }
}

// ---------------------------------------------------------------------------
// K2 (tail): mm1+bn1, grid sync, mm2+bn2+out. 64 blocks x 256 threads.
// ---------------------------------------------------------------------------
__global__ void __launch_bounds__(256) tail_kernel(
    const float* __restrict__ w1, const float* __restrict__ b1,
    const float* __restrict__ gamma1, const float* __restrict__ beta1,
    const float* __restrict__ w2, const float* __restrict__ b2,
    const float* __restrict__ gamma2, const float* __restrict__ beta2,
    float* __restrict__ out)
{
    __shared__ float sh[SH_FLOATS];
    const int tid  = threadIdx.x;
    const int lane = tid & 31;
    const int warp = tid >> 5;

    // ---- Phase B: mm1 + bn1, block j = output column j ----
    {
        float* ws    = sh;        // [512] w1 row j
        float* h1s   = sh + 512;  // [64]
        float* stats = sh + 576;  // [2]
        const int j = blockIdx.x;

        // Stage w1 row j (coalesced); prefetch this block's phase-C w2 slice
        // (8 consecutive rows = 2 KB = 16 lines) into L2.
        for (int i = tid; i < Cc; i += 256) ws[i] = w1[(size_t)j * Cc + i];
        if (tid < 16) {
            const char* p = (const char*)(w2 + (size_t)blockIdx.x * 8 * Cr) + tid * 128;
            asm volatile("prefetch.global.L2 [%0];" :: "l"(p));
        }
        __syncthreads();

        // 8 warps x 8 rows; batch ALL 128 loads per warp before any reduce.
        float acc[8];
        #pragma unroll
        for (int k = 0; k < 8; k++) acc[k] = 0.f;

        #pragma unroll
        for (int i = 0; i < 16; i++) {
            const int col = i * 32 + lane;
            const float wv = ws[col];
            #pragma unroll
            for (int k = 0; k < 8; k++)
                acc[k] += g_buf[(size_t)(warp * 8 + k) * Cc + col] * wv;
        }

        const float b1j = b1[j];
        #pragma unroll
        for (int k = 0; k < 8; k++) {
            float v = acc[k];
            #pragma unroll
            for (int off = 16; off > 0; off >>= 1)
                v += __shfl_down_sync(0xffffffffu, v, off);
            if (lane == 0) h1s[warp * 8 + k] = v + b1j;
        }
        __syncthreads();

        if (warp == 0) {
            float a = h1s[lane], b = h1s[lane + 32];
            float s  = a + b;
            float ss = a * a + b * b;
            #pragma unroll
            for (int off = 16; off > 0; off >>= 1) {
                s  += __shfl_down_sync(0xffffffffu, s,  off);
                ss += __shfl_down_sync(0xffffffffu, ss, off);
            }
            if (lane == 0) {
                float mu  = s * (1.0f / TB);
                float var = ss * (1.0f / TB) - mu * mu;
                if (var < 0.f) var = 0.f;
                stats[0] = mu;
                stats[1] = rsqrtf(var + 1e-5f) * gamma1[j];
            }
        }
        __syncthreads();

        // Transposed, coalesced store: h1nT[j][r]
        if (tid < TB)
            h1nT_buf[j * TB + tid] = (h1s[tid] - stats[0]) * stats[1] + beta1[j];
    }

    // ---- grid-wide barrier (monotonic; 64 arrivals per launch) ----
    {
        __threadfence();
        __syncthreads();
        if (tid == 0) {
            unsigned v = atomicAdd(&g_arrive, 1u) + 1u;
            unsigned B = (v + (unsigned)TAIL_NB - 1u) / (unsigned)TAIL_NB;
            if (v == B * (unsigned)TAIL_NB) g_release = B;
            while (g_release < B) { __nanosleep(32); }
            __threadfence();
        }
        __syncthreads();
    }

    // ---- Phase C: mm2 + bn2 + out; block owns 8 consecutive columns ----
    {
        float* hT   = sh;                  // [64*65] padded: hT[j*65 + r]
        float* w2s  = sh + 64 * 65;        // [512] rows c0..c0+7 of w2
        float* wsum = sh + 64 * 65 + 512;  // [32]
        const int c0 = blockIdx.x * 8;

        // Stage h1nT (coalesced) into padded smem.
        for (int i = tid; i < Cr * TB; i += 256)
            hT[(i >> 6) * 65 + (i & 63)] = h1nT_buf[i];
        // Stage 8 consecutive w2 rows = 512 consecutive floats (L2-hot).
        for (int i = tid; i < 8 * Cr; i += 256)
            w2s[i] = w2[(size_t)c0 * Cr + i];
        __syncthreads();

        const int q  = tid >> 6;        // column group 0..3
        const int r  = tid & 63;        // row 0..63
        const int gw = (tid >> 5) & 1;  // warp within group

        #pragma unroll
        for (int p = 0; p < 2; p++) {
            const int k = p * 4 + q;
            const int c = c0 + k;

            float acc = 0.f;
            const float* __restrict__ wr = w2s + k * Cr;
            #pragma unroll
            for (int j = 0; j < Cr; j++)
                acc += hT[j * 65 + r] * wr[j];
            const float h = acc + b2[c];

            float s = h, ss = h * h;
            #pragma unroll
            for (int off = 16; off > 0; off >>= 1) {
                s  += __shfl_down_sync(0xffffffffu, s,  off);
                ss += __shfl_down_sync(0xffffffffu, ss, off);
            }
            float* wp = wsum + (p * 16 + q * 4 + gw * 2);
            if (lane == 0) { wp[0] = s; wp[1] = ss; }
            __syncthreads();

            const float* w0 = wsum + (p * 16 + q * 4);
            const float S  = w0[0] + w0[2];
            const float SS = w0[1] + w0[3];
            const float mu = S * (1.0f / TB);
            float var = SS * (1.0f / TB) - mu * mu;
            if (var < 0.f) var = 0.f;
            const float sc = rsqrtf(var + 1e-5f) * gamma2[c];
            out[r * Cc + c] = (h - mu) * sc + beta2[c];
        }
    }
}

// ---------------------------------------------------------------------------
extern "C" void kernel_launch(void* const* d_in, const int* in_sizes, int n_in,
                              void* d_out, int out_size) {
    const float* x      = (const float*)d_in[0];
    const float* w1     = (const float*)d_in[1];
    const float* b1     = (const float*)d_in[2];
    const float* gamma1 = (const float*)d_in[3];
    const float* beta1  = (const float*)d_in[4];
    const float* w2     = (const float*)d_in[5];
    const float* b2     = (const float*)d_in[6];
    const float* gamma2 = (const float*)d_in[7];
    const float* beta2  = (const float*)d_in[8];
    float* out = (float*)d_out;

    int dev = 0, sms = 0, maxb = 0;
    cudaGetDevice(&dev);
    cudaDeviceGetAttribute(&sms, cudaDevAttrMultiProcessorCount, dev);
    cudaOccupancyMaxActiveBlocksPerMultiprocessor(&maxb, lif_gap_kernel, 256, 0);
    if (sms < 1) sms = 1;
    if (maxb < 1) maxb = 1;
    int nb1 = sms * maxb;
    if (nb1 > NTASK) nb1 = NTASK;

    lif_gap_kernel<<<nb1, 256>>>(x, nb1);
    tail_kernel<<<TAIL_NB, 256>>>(w1, b1, gamma1, beta1,
                                  w2, b2, gamma2, beta2, out);
}

// round 8
// speedup vs baseline: 1.0317x; 1.0317x over previous
#include <cuda_runtime.h>

// Problem constants
static constexpr int Tt = 4;
static constexpr int Bb = 16;
static constexpr int Cc = 512;
static constexpr int Nn = 1024;
static constexpr int Cr = 64;
static constexpr int TB = Tt * Bb;     // 64 rows
static constexpr int BC = Bb * Cc;     // 8192 channels

// Scratch (allocation-free: __device__ globals)
__device__ float g_buf[TB * Cc];       // GAP output [64, 512] row-major [r][c]
__device__ float h1nT_buf[Cr * TB];    // bn1 output TRANSPOSED [j][r]

// ---------------------------------------------------------------------------
// K1: LIF multistep (TAU=2, hard reset, v_th=1) + GAP over N.
// EXACT R2 shape (proven 25.7us): flat 4096 blocks, one block per TWO
// channels, 256 threads, 8 front-batched LDG.128 per thread.
// ---------------------------------------------------------------------------
__global__ void __launch_bounds__(256) lif_gap_kernel(const float* __restrict__ x) {
    const int bc0 = blockIdx.x * 2;
    const int bc1 = bc0 + 1;
    const int tid = threadIdx.x;

    const float4* __restrict__ xp = reinterpret_cast<const float4*>(x);

    float4 xa[Tt], xb[Tt];
    #pragma unroll
    for (int t = 0; t < Tt; t++) {
        xa[t] = xp[(size_t)(t * BC + bc0) * 256 + tid];
        xb[t] = xp[(size_t)(t * BC + bc1) * 256 + tid];
    }

    float va0=0.f, va1=0.f, va2=0.f, va3=0.f;
    float vb0=0.f, vb1=0.f, vb2=0.f, vb3=0.f;
    float c8[8];

    #pragma unroll
    for (int t = 0; t < Tt; t++) {
        float ca = 0.f, cb = 0.f;
        va0 = (va0 + xa[t].x) * 0.5f; { float s = (va0 >= 1.f) ? 1.f : 0.f; ca += s; va0 *= (1.f - s); }
        va1 = (va1 + xa[t].y) * 0.5f; { float s = (va1 >= 1.f) ? 1.f : 0.f; ca += s; va1 *= (1.f - s); }
        va2 = (va2 + xa[t].z) * 0.5f; { float s = (va2 >= 1.f) ? 1.f : 0.f; ca += s; va2 *= (1.f - s); }
        va3 = (va3 + xa[t].w) * 0.5f; { float s = (va3 >= 1.f) ? 1.f : 0.f; ca += s; va3 *= (1.f - s); }
        vb0 = (vb0 + xb[t].x) * 0.5f; { float s = (vb0 >= 1.f) ? 1.f : 0.f; cb += s; vb0 *= (1.f - s); }
        vb1 = (vb1 + xb[t].y) * 0.5f; { float s = (vb1 >= 1.f) ? 1.f : 0.f; cb += s; vb1 *= (1.f - s); }
        vb2 = (vb2 + xb[t].z) * 0.5f; { float s = (vb2 >= 1.f) ? 1.f : 0.f; cb += s; vb2 *= (1.f - s); }
        vb3 = (vb3 + xb[t].w) * 0.5f; { float s = (vb3 >= 1.f) ? 1.f : 0.f; cb += s; vb3 *= (1.f - s); }
        c8[t]     = ca;
        c8[t + 4] = cb;
    }

    __shared__ float sdata[8][8];   // [warp][val]
    const int lane = tid & 31;
    const int warp = tid >> 5;

    #pragma unroll
    for (int k = 0; k < 8; k++) {
        float val = c8[k];
        #pragma unroll
        for (int off = 16; off > 0; off >>= 1)
            val += __shfl_down_sync(0xffffffffu, val, off);
        if (lane == 0) sdata[warp][k] = val;
    }
    __syncthreads();

    if (tid < 8) {
        float s = 0.f;
        #pragma unroll
        for (int w = 0; w < 8; w++) s += sdata[w][tid];
        const int t  = tid & 3;
        const int bc = (tid < 4) ? bc0 : bc1;
        g_buf[t * BC + bc] = s * (1.0f / (float)Nn);
    }
}

// ---------------------------------------------------------------------------
// T1: mm1 + bn1. 64 blocks (one per output column j) x 512 threads.
// 16 warps x 4 rows; each warp front-batches 64 g_buf loads across its 4
// row-accumulators. BN1 is per-column -> fully block-local. Writes h1n
// TRANSPOSED (contiguous 64 floats per column).
// ---------------------------------------------------------------------------
__global__ void __launch_bounds__(512) t1_kernel(const float* __restrict__ w1,
                                                 const float* __restrict__ b1,
                                                 const float* __restrict__ gamma1,
                                                 const float* __restrict__ beta1) {
    __shared__ float ws[Cc];
    __shared__ float h1s[TB];
    __shared__ float stats[2];

    const int j    = blockIdx.x;
    const int tid  = threadIdx.x;
    const int lane = tid & 31;
    const int warp = tid >> 5;      // 0..15

    ws[tid] = w1[(size_t)j * Cc + tid];
    __syncthreads();

    // Warp w owns rows w*4 .. w*4+3.
    const float* __restrict__ g0 = g_buf + (size_t)(warp * 4 + 0) * Cc;
    const float* __restrict__ g1 = g_buf + (size_t)(warp * 4 + 1) * Cc;
    const float* __restrict__ g2 = g_buf + (size_t)(warp * 4 + 2) * Cc;
    const float* __restrict__ g3 = g_buf + (size_t)(warp * 4 + 3) * Cc;

    float a0 = 0.f, a1 = 0.f, a2 = 0.f, a3 = 0.f;
    #pragma unroll
    for (int i = 0; i < 16; i++) {
        const int col = i * 32 + lane;
        const float wv = ws[col];
        a0 += g0[col] * wv;
        a1 += g1[col] * wv;
        a2 += g2[col] * wv;
        a3 += g3[col] * wv;
    }

    #pragma unroll
    for (int off = 16; off > 0; off >>= 1) {
        a0 += __shfl_down_sync(0xffffffffu, a0, off);
        a1 += __shfl_down_sync(0xffffffffu, a1, off);
        a2 += __shfl_down_sync(0xffffffffu, a2, off);
        a3 += __shfl_down_sync(0xffffffffu, a3, off);
    }
    if (lane == 0) {
        const float b1j = b1[j];
        h1s[warp * 4 + 0] = a0 + b1j;
        h1s[warp * 4 + 1] = a1 + b1j;
        h1s[warp * 4 + 2] = a2 + b1j;
        h1s[warp * 4 + 3] = a3 + b1j;
    }
    __syncthreads();

    if (warp == 0) {
        float a = h1s[lane], b = h1s[lane + 32];
        float s  = a + b;
        float ss = a * a + b * b;
        #pragma unroll
        for (int off = 16; off > 0; off >>= 1) {
            s  += __shfl_down_sync(0xffffffffu, s,  off);
            ss += __shfl_down_sync(0xffffffffu, ss, off);
        }
        if (lane == 0) {
            float mu  = s * (1.0f / TB);
            float var = ss * (1.0f / TB) - mu * mu;
            if (var < 0.f) var = 0.f;
            stats[0] = mu;
            stats[1] = rsqrtf(var + 1e-5f) * gamma1[j];
        }
    }
    __syncthreads();

    if (tid < TB)
        h1nT_buf[j * TB + tid] = (h1s[tid] - stats[0]) * stats[1] + beta1[j];
}

// ---------------------------------------------------------------------------
// T2: mm2 + bn2 + out. 512 blocks (one per output column c) x 256 threads.
// All 256 threads stage h1nT (float4, coalesced) into padded smem; threads
// 0..63 compute the 64-deep dot for their row, then block-local BN2.
// ---------------------------------------------------------------------------
__global__ void __launch_bounds__(256) t2_kernel(const float* __restrict__ w2,
                                                 const float* __restrict__ b2,
                                                 const float* __restrict__ gamma2,
                                                 const float* __restrict__ beta2,
                                                 float* __restrict__ out) {
    __shared__ float hT[Cr * (TB + 1)];  // hT[j*65 + r]
    __shared__ float w2s[Cr];
    __shared__ float wsum[4];

    const int c    = blockIdx.x;
    const int tid  = threadIdx.x;
    const int lane = tid & 31;
    const int warp = tid >> 5;

    // Stage h1nT: 4096 floats = 1024 float4, 4 per thread, coalesced.
    {
        const float4* __restrict__ hp = reinterpret_cast<const float4*>(h1nT_buf);
        #pragma unroll
        for (int u = 0; u < 4; u++) {
            const int i4 = u * 256 + tid;
            float4 v = hp[i4];
            const int i  = i4 * 4;
            const int jj = i >> 6, rr = i & 63;
            float* d = &hT[jj * 65 + rr];
            d[0] = v.x; d[1] = v.y; d[2] = v.z; d[3] = v.w;
        }
    }
    if (tid < Cr) w2s[tid] = w2[(size_t)c * Cr + tid];
    __syncthreads();

    float h = 0.f;
    if (tid < TB) {
        const int r = tid;
        float acc = 0.f;
        #pragma unroll
        for (int j = 0; j < Cr; j++)
            acc += hT[j * 65 + r] * w2s[j];
        h = acc + b2[c];

        float s = h, ss = h * h;
        #pragma unroll
        for (int off = 16; off > 0; off >>= 1) {
            s  += __shfl_down_sync(0xffffffffu, s,  off);
            ss += __shfl_down_sync(0xffffffffu, ss, off);
        }
        if (lane == 0) { wsum[warp * 2] = s; wsum[warp * 2 + 1] = ss; }
    }
    __syncthreads();

    if (tid < TB) {
        const float S  = wsum[0] + wsum[2];
        const float SS = wsum[1] + wsum[3];
        const float mu = S * (1.0f / TB);
        float var = SS * (1.0f / TB) - mu * mu;
        if (var < 0.f) var = 0.f;
        const float sc = rsqrtf(var + 1e-5f) * gamma2[c];
        out[tid * Cc + c] = (h - mu) * sc + beta2[c];
    }
}

// ---------------------------------------------------------------------------
extern "C" void kernel_launch(void* const* d_in, const int* in_sizes, int n_in,
                              void* d_out, int out_size) {
    const float* x      = (const float*)d_in[0];
    const float* w1     = (const float*)d_in[1];
    const float* b1     = (const float*)d_in[2];
    const float* gamma1 = (const float*)d_in[3];
    const float* beta1  = (const float*)d_in[4];
    const float* w2     = (const float*)d_in[5];
    const float* b2     = (const float*)d_in[6];
    const float* gamma2 = (const float*)d_in[7];
    const float* beta2  = (const float*)d_in[8];
    float* out = (float*)d_out;

    lif_gap_kernel<<<BC / 2, 256>>>(x);
    t1_kernel<<<Cr, 512>>>(w1, b1, gamma1, beta1);
    t2_kernel<<<Cc, 256>>>(w2, b2, gamma2, beta2, out);
}